// round 2
// baseline (speedup 1.0000x reference)
#include <cuda_runtime.h>
#include <cstdint>

#define TOTAL   488418
#define BATCHN  10
#define NPROB   80
#define MAXEQ   512
#define HID     256
#define OUT_TOTAL (BATCHN*TOTAL)

__constant__ int c_sln[8] = {160000,400,160000,400,160000,400,7200,18};
__constant__ int c_slo[8] = {0,160000,160400,320400,320800,480800,481200,488400};

__device__ float    g_h[BATCHN*HID];
__device__ unsigned g_keys[BATCHN*TOTAL];      // ~19.5 MB static scratch
__device__ unsigned g_T[NPROB];
__device__ int      g_r[NPROB];
__device__ int      g_eqcnt[NPROB];
__device__ int      g_eqidx[NPROB*MAXEQ];

// ---------------- threefry-2x32 (key = (0, 42)) ----------------
__device__ __forceinline__ unsigned rotl(unsigned x, int d) {
    return __funnelshift_l(x, x, d);
}

__device__ __forceinline__ uint2 threefry2x32(unsigned c0, unsigned c1) {
    const unsigned K0 = 0u, K1 = 42u, K2 = 0x1BD11BDAu ^ K0 ^ K1;
    unsigned x0 = c0 + K0, x1 = c1 + K1;
#define TFR(r) { x0 += x1; x1 = rotl(x1, (r)); x1 ^= x0; }
    TFR(13) TFR(15) TFR(26) TFR(6)   x0 += K1; x1 += K2 + 1u;
    TFR(17) TFR(29) TFR(16) TFR(24)  x0 += K2; x1 += K0 + 2u;
    TFR(13) TFR(15) TFR(26) TFR(6)   x0 += K0; x1 += K1 + 3u;
    TFR(17) TFR(29) TFR(16) TFR(24)  x0 += K1; x1 += K2 + 4u;
    TFR(13) TFR(15) TFR(26) TFR(6)   x0 += K2; x1 += K0 + 5u;
#undef TFR
    return make_uint2(x0, x1);
}

// partitionable threefry bits for element e (size < 2^32 -> counter hi = 0)
__device__ __forceinline__ unsigned pbits(unsigned e) {
    uint2 r = threefry2x32(0u, e);
    return r.x ^ r.y;
}

// uniform in [tiny,1) then gumbel, as jax.random.gumbel lowers
__device__ __forceinline__ float gumbel_from_bits(unsigned bits) {
    float uf = __uint_as_float((bits >> 9) | 0x3F800000u) - 1.0f;
    uf = fmaxf(uf, 1.17549435e-38f);
    return -logf(-logf(uf));
}

// float -> monotonically increasing uint32
__device__ __forceinline__ unsigned keymap(float z) {
    unsigned u = __float_as_uint(z);
    return u ^ (unsigned)(((int)u >> 31) | 0x80000000);
}

// ---------------- packed f32x2 helpers ----------------
__device__ __forceinline__ unsigned long long pack_dup(float x) {
    unsigned long long r; unsigned xi = __float_as_uint(x);
    asm("mov.b64 %0, {%1, %1};" : "=l"(r) : "r"(xi));
    return r;
}
__device__ __forceinline__ void fma2(unsigned long long &d,
                                     unsigned long long a, unsigned long long b) {
    asm("fma.rn.f32x2 %0, %1, %2, %0;" : "+l"(d) : "l"(a), "l"(b));
}
__device__ __forceinline__ void unpack2(unsigned long long v, float &lo, float &hi) {
    unsigned a, b;
    asm("mov.b64 {%0, %1}, %2;" : "=r"(a), "=r"(b) : "l"(v));
    lo = __uint_as_float(a); hi = __uint_as_float(b);
}

// ---------------- kernel 1: h = relu(emb @ W1 + b1) ----------------
__global__ void k_hidden(const float* __restrict__ emb,
                         const float* __restrict__ W1,
                         const float* __restrict__ b1) {
    __shared__ float se[BATCHN*10];
    int j = threadIdx.x;                // 256 threads
    if (j < BATCHN*10) se[j] = emb[j];
    __syncthreads();
    float bj = b1[j];
#pragma unroll
    for (int b = 0; b < BATCHN; b++) {
        float acc = bj;
#pragma unroll
        for (int i = 0; i < 10; i++)
            acc = fmaf(se[b*10+i], __ldg(&W1[i*HID + j]), acc);
        g_h[b*HID + j] = fmaxf(acc, 0.0f);
    }
}

// ---------------- kernel 2: GEMV + bias + gumbel + keymap ----------------
__global__ void __launch_bounds__(256) k_main(const float* __restrict__ W2,
                                              const float* __restrict__ b2) {
    // sh2[j*5 + bp] = packed (h[2bp][j], h[2bp+1][j])
    __shared__ unsigned long long sh2[HID*5];
    for (int idx = threadIdx.x; idx < HID*5; idx += 256) {
        int j = idx / 5, bp = idx % 5;
        unsigned long long v;
        unsigned a = __float_as_uint(g_h[(2*bp)*HID + j]);
        unsigned b = __float_as_uint(g_h[(2*bp+1)*HID + j]);
        asm("mov.b64 %0, {%1, %2};" : "=l"(v) : "r"(a), "r"(b));
        sh2[idx] = v;
    }
    __syncthreads();

    int c0 = (blockIdx.x*256 + threadIdx.x)*2;
    if (c0 >= TOTAL) return;

    unsigned long long accA[5], accB[5];
#pragma unroll
    for (int bp = 0; bp < 5; bp++) { accA[bp] = 0ull; accB[bp] = 0ull; }

#pragma unroll 4
    for (int j = 0; j < HID; j++) {
        float2 w = __ldg(reinterpret_cast<const float2*>(W2 + (size_t)j*TOTAL + c0));
        unsigned long long wa = pack_dup(w.x);
        unsigned long long wb = pack_dup(w.y);
#pragma unroll
        for (int bp = 0; bp < 5; bp++) {
            unsigned long long hp = sh2[j*5 + bp];
            fma2(accA[bp], hp, wa);
            fma2(accB[bp], hp, wb);
        }
    }

    float2 bias = __ldg(reinterpret_cast<const float2*>(b2 + c0));
    float mv0[BATCHN], mv1[BATCHN];
#pragma unroll
    for (int bp = 0; bp < 5; bp++) {
        float lo, hi;
        unpack2(accA[bp], lo, hi);
        mv0[2*bp]   = lo + bias.x;  mv0[2*bp+1] = hi + bias.x;
        unpack2(accB[bp], lo, hi);
        mv1[2*bp]   = lo + bias.y;  mv1[2*bp+1] = hi + bias.y;
    }

    // partitionable-threefry gumbel per element e = b*TOTAL + c
#pragma unroll
    for (int b = 0; b < BATCHN; b++) {
        unsigned e0 = (unsigned)b * (unsigned)TOTAL + (unsigned)c0;
        unsigned kk0 = keymap(mv0[b] + gumbel_from_bits(pbits(e0)));
        unsigned kk1 = keymap(mv1[b] + gumbel_from_bits(pbits(e0 + 1u)));
        *reinterpret_cast<uint2*>(&g_keys[(size_t)b*TOTAL + c0]) = make_uint2(kk0, kk1);
    }
}

// ---------------- kernel 3: per-(row,slice) radix select of k-th largest ----------------
__global__ void __launch_bounds__(1024) k_select() {
    int p = blockIdx.x;
    int b = p >> 3, s = p & 7;
    int n = c_sln[s];
    int base = b*TOTAL + c_slo[s];
    int k = n >> 1;

    __shared__ unsigned hist[256];
    __shared__ unsigned sprefix;
    __shared__ int skk;
    __shared__ int seqc;
    if (threadIdx.x == 0) { sprefix = 0u; skk = k; seqc = 0; }
    __syncthreads();

    for (int pass = 3; pass >= 0; --pass) {
        if (threadIdx.x < 256) hist[threadIdx.x] = 0u;
        __syncthreads();
        int shift = pass * 8;
        unsigned himask = (pass == 3) ? 0u : (0xFFFFFFFFu << (shift + 8));
        unsigned pref = sprefix;
        for (int i = threadIdx.x; i < n; i += 1024) {
            unsigned key = g_keys[base + i];
            if ((key & himask) == pref)
                atomicAdd(&hist[(key >> shift) & 255u], 1u);
        }
        __syncthreads();
        if (threadIdx.x == 0) {
            int kk = skk; unsigned cum = 0; int v = 255;
            for (; v > 0; --v) {
                if (cum + hist[v] >= (unsigned)kk) break;
                cum += hist[v];
            }
            sprefix = pref | ((unsigned)v << shift);
            skk = kk - (int)cum;
        }
        __syncthreads();
    }

    unsigned T = sprefix;
    for (int i = threadIdx.x; i < n; i += 1024) {
        if (g_keys[base + i] == T) {
            int pos = atomicAdd(&seqc, 1);
            if (pos < MAXEQ) g_eqidx[p*MAXEQ + pos] = i;
        }
    }
    __syncthreads();
    if (threadIdx.x == 0) {
        g_T[p] = T;
        g_r[p] = skk;                       // how many equal-to-threshold accepted
        g_eqcnt[p] = min(seqc, MAXEQ);
    }
}

// ---------------- kernel 4: emit hard mask ----------------
__global__ void k_mask(float* __restrict__ out) {
    int o = blockIdx.x*256 + threadIdx.x;
    if (o >= OUT_TOTAL) return;
    int s = 0;
#pragma unroll
    for (int t = 1; t < 8; t++)
        if (o >= 10*c_slo[t]) s = t;
    int n   = c_sln[s];
    int rel = o - 10*c_slo[s];
    int b   = rel / n;
    int i   = rel - b*n;
    int p   = b*8 + s;
    unsigned key = g_keys[(size_t)b*TOTAL + c_slo[s] + i];
    unsigned T   = g_T[p];
    float v;
    if (key != T) {
        v = (key > T) ? 1.0f : 0.0f;
    } else {
        int r = g_r[p], cnt = g_eqcnt[p], rank = 0;
        for (int q = 0; q < cnt; q++)
            rank += (g_eqidx[p*MAXEQ + q] < i);  // lowest-index ties win (JAX top_k)
        v = (rank < r) ? 1.0f : 0.0f;
    }
    out[o] = v;
}

// ---------------- launch ----------------
extern "C" void kernel_launch(void* const* d_in, const int* in_sizes, int n_in,
                              void* d_out, int out_size) {
    const float* emb = (const float*)d_in[1];   // embedding_input [10,10]
    const float* W1  = (const float*)d_in[2];   // [10,256]
    const float* b1  = (const float*)d_in[3];   // [256]
    const float* W2  = (const float*)d_in[4];   // [256, TOTAL]
    const float* b2  = (const float*)d_in[5];   // [TOTAL]
    float* out = (float*)d_out;

    k_hidden<<<1, 256>>>(emb, W1, b1);
    k_main<<<(TOTAL/2 + 255)/256, 256>>>(W2, b2);
    k_select<<<NPROB, 1024>>>();
    k_mask<<<(OUT_TOTAL + 255)/256, 256>>>(out);
}